// round 14
// baseline (speedup 1.0000x reference)
#include <cuda_runtime.h>
#include <cuda_fp16.h>
#include <math.h>

// Problem constants (fixed by reference setup_inputs)
constexpr int B  = 64;
constexpr int I  = 2048;
constexpr int P  = 16;
constexpr int J  = 32;          // == warp size: lane j owns capsule j
constexpr int D  = 16;
constexpr int JD = J * D;       // 512

constexpr int NIB   = 32;       // i-blocks -> 2048 items per phase
constexpr int IPB   = I / NIB;  // 64 i's per item
constexpr int NITEM = NIB * B;  // 2048
constexpr int NCTA  = 592;      // 148 SMs x 4 CTAs (co-resident on 148/152-SM parts)

// Scratch (device globals; zero-initialized at load; invariants restored per run)
__device__ __half g_uhat[(size_t)B * I * JD];  // 128 MB fp16  [b,i,j,d]
__device__ float  g_s[B * J * D];              // 128 KB  s accumulator (starts 0)
__device__ float  g_vsum[B * J * D];           // 128 KB  running v0(+v1)
__device__ unsigned g_tick[3];                 // monotonic ticket counters
__device__ unsigned g_arrive;                  // barrier arrive (self-resetting)
__device__ unsigned g_gen;                     // barrier generation (monotonic)

// ---- packed f32x2 helpers (gemm) -------------------------------------------
__device__ __forceinline__ unsigned long long pack2(float lo, float hi) {
    unsigned long long r;
    asm("mov.b64 %0,{%1,%2};" : "=l"(r) : "f"(lo), "f"(hi));
    return r;
}
#define FMA_X2(a, x, c) asm("fma.rn.f32x2 %0, %1, %2, %0;" : "+l"(a) : "l"(x), "l"(c))

// ---------------------------------------------------------------------------
// Kernel 1: u_hat[b,i,jd] = sum_p inputs[b,i,p] * W[i,jd,p], stored fp16.
// One CTA per i. R14: one jd per thread per pass (2 passes) -> weight regs
// halve (32), total ~52 regs -> __launch_bounds__(256,4) doubles occupancy
// (was register-limited to 2 CTAs/SM). x-pack (b-pair) from one broadcast
// LDS.64; outputs are two coalesced STG.16 per q.
// ---------------------------------------------------------------------------
__global__ __launch_bounds__(256, 4) void gemm_uhat(const float* __restrict__ in,
                                                    const float* __restrict__ W) {
    const int i = blockIdx.x;
    const int t = threadIdx.x;

    __shared__ __align__(16) float Ws[JD * 17];    // padded rows: bank-safe
    __shared__ __align__(16) float insT[P][B + 2]; // p-major: 8B-aligned float2

    // stage W[i] (32 KB, streaming hint: keep u_hat resident in L2 instead)
    const float4* Wg = reinterpret_cast<const float4*>(W + (size_t)i * JD * P);
#pragma unroll
    for (int k = 0; k < 8; k++) {
        int e = t + k * 256;             // float4 index 0..2047
        float4 v = __ldcs(&Wg[e]);
        float* dst = &Ws[(e >> 2) * 17 + (e & 3) * 4];
        dst[0] = v.x; dst[1] = v.y; dst[2] = v.z; dst[3] = v.w;
    }
    // stage inputs[:, i, :] transposed -> insT[p][b]
#pragma unroll
    for (int k = 0; k < 4; k++) {
        int e = t + k * 256;             // 0..1023
        int b = e >> 4, p = e & 15;
        insT[p][b] = in[((size_t)b * I + i) * P + p];
    }
    __syncthreads();

#pragma unroll
    for (int pass = 0; pass < 2; pass++) {
        const int jd = t + pass * 256;

        // splat this jd's W row into f32x2 registers (32 regs)
        unsigned long long wreg[16];
#pragma unroll
        for (int p = 0; p < 16; p++) {
            float a = Ws[jd * 17 + p];
            asm("mov.b64 %0,{%1,%1};" : "=l"(wreg[p]) : "f"(a));
        }

        __half* ubase = g_uhat + (size_t)i * JD + jd;
#pragma unroll 4
        for (int q = 0; q < 32; q++) {   // batch pair (2q, 2q+1)
            unsigned long long a0 = 0ull;
#pragma unroll
            for (int p = 0; p < 16; p++) {
                float2 xp = *reinterpret_cast<const float2*>(&insT[p][2 * q]);
                unsigned long long x = pack2(xp.x, xp.y);
                FMA_X2(a0, x, wreg[p]);
            }
            float lo, hi;
            asm("mov.b64 {%0,%1}, %2;" : "=f"(lo), "=f"(hi) : "l"(a0));
            ubase[(size_t)(2 * q)     * I * JD] = __float2half_rn(lo);
            ubase[(size_t)(2 * q + 1) * I * JD] = __float2half_rn(hi);
        }
    }
}

// ---------------------------------------------------------------------------
// Grid barrier: arrive counter (self-resetting) + monotonic generation.
// base = generation snapshot at kernel entry; target = base + k. Wrap-safe,
// replay-safe (no resets). All NCTA CTAs are co-resident by construction.
// ---------------------------------------------------------------------------
__device__ __forceinline__ void grid_bar(unsigned base, unsigned k) {
    __syncthreads();
    if (threadIdx.x == 0) {
        __threadfence();
        if (atomicAdd(&g_arrive, 1u) == NCTA - 1) {
            g_arrive = 0;
            __threadfence();
            atomicExch(&g_gen, base + k);
        } else {
            while ((unsigned)(*(volatile unsigned*)&g_gen - base) < k)
                __nanosleep(64);
        }
        __threadfence();
    }
    __syncthreads();
}

// ---------------------------------------------------------------------------
// One routing item (b, ib): R11 compute body (IPB=64).
//   MODE 0: c = 1/32.   MODE 1/2: c = softmax_j(u . vsum), ILP-2 butterflies.
// fp16 HFMA2 dot + fp16 accumulate flushed to fp32 every 4 i's.
// ---------------------------------------------------------------------------
template <int MODE>
__device__ __forceinline__ void do_item(int b, int ib, float (*sacc)[D + 1]) {
    const int w = threadIdx.x >> 5;
    const int j = threadIdx.x & 31;

    __half2 hv[8];
    if (MODE > 0) {
        const float4* vp = reinterpret_cast<const float4*>(g_vsum + (b * J + j) * D);
#pragma unroll
        for (int k = 0; k < 4; k++) {
            float4 q = vp[k];
            hv[2*k]   = __floats2half2_rn(q.x, q.y);
            hv[2*k+1] = __floats2half2_rn(q.z, q.w);
        }
    }

    float  facc[16];
    __half2 hacc[8];
    const __half2 hz = __floats2half2_rn(0.f, 0.f);
#pragma unroll
    for (int d = 0; d < 16; d++) facc[d] = 0.f;
#pragma unroll
    for (int m = 0; m < 8; m++) hacc[m] = hz;

    const size_t row = (size_t)b * I + (size_t)ib * IPB;

    if (MODE == 0) {
#pragma unroll
        for (int ii = 0; ii < IPB; ii += 32) {
#pragma unroll
            for (int k = 0; k < 4; k++) {
                const __half* up = g_uhat + (row + w + ii + 8 * k) * JD + j * D;
                uint4 q0 = *reinterpret_cast<const uint4*>(up);
                uint4 q1 = *reinterpret_cast<const uint4*>(up + 8);
                const __half2* h0 = reinterpret_cast<const __half2*>(&q0);
                const __half2* h1 = reinterpret_cast<const __half2*>(&q1);
#pragma unroll
                for (int m = 0; m < 4; m++) {
                    hacc[m]   = __hadd2(hacc[m],   h0[m]);
                    hacc[4+m] = __hadd2(hacc[4+m], h1[m]);
                }
            }
#pragma unroll
            for (int m = 0; m < 8; m++) {
                float2 f = __half22float2(hacc[m]);
                facc[2*m] += f.x;  facc[2*m+1] += f.y;
                hacc[m] = hz;
            }
        }
#pragma unroll
        for (int d = 0; d < 16; d++) facc[d] *= (1.f / 32.f);
    } else {
#pragma unroll
        for (int gg = 0; gg < IPB / 32; gg++) {
#pragma unroll
            for (int h = 0; h < 2; h++) {
                const int g = 2 * gg + h;
                const __half* upA = g_uhat + (row + w + 16 * g) * JD + j * D;
                const __half* upB = upA + 8 * JD;
                uint4 qa0 = *reinterpret_cast<const uint4*>(upA);
                uint4 qa1 = *reinterpret_cast<const uint4*>(upA + 8);
                uint4 qb0 = *reinterpret_cast<const uint4*>(upB);
                uint4 qb1 = *reinterpret_cast<const uint4*>(upB + 8);
                const __half2* ha0 = reinterpret_cast<const __half2*>(&qa0);
                const __half2* ha1 = reinterpret_cast<const __half2*>(&qa1);
                const __half2* hb0 = reinterpret_cast<const __half2*>(&qb0);
                const __half2* hb1 = reinterpret_cast<const __half2*>(&qb1);

                __half2 dA = __hmul2(ha0[0], hv[0]);
                __half2 dB = __hmul2(hb0[0], hv[0]);
#pragma unroll
                for (int m = 1; m < 4; m++) {
                    dA = __hfma2(ha0[m], hv[m], dA);
                    dB = __hfma2(hb0[m], hv[m], dB);
                }
#pragma unroll
                for (int m = 0; m < 4; m++) {
                    dA = __hfma2(ha1[m], hv[4+m], dA);
                    dB = __hfma2(hb1[m], hv[4+m], dB);
                }
                float2 fA = __half22float2(dA);
                float2 fB = __half22float2(dB);
                float tA = fA.x + fA.y;
                float tB = fB.x + fB.y;

                float eA = __expf(tA);
                float eB = __expf(tB);
                float sA = eA, sB = eB;
#pragma unroll
                for (int off = 16; off; off >>= 1) {
                    sA += __shfl_xor_sync(0xffffffffu, sA, off);
                    sB += __shfl_xor_sync(0xffffffffu, sB, off);
                }
                __half2 cA2 = __float2half2_rn(__fdividef(eA, sA));
                __half2 cB2 = __float2half2_rn(__fdividef(eB, sB));

#pragma unroll
                for (int m = 0; m < 4; m++) {
                    hacc[m]   = __hfma2(ha0[m], cA2, hacc[m]);
                    hacc[4+m] = __hfma2(ha1[m], cA2, hacc[4+m]);
                    hacc[m]   = __hfma2(hb0[m], cB2, hacc[m]);
                    hacc[4+m] = __hfma2(hb1[m], cB2, hacc[4+m]);
                }
            }
#pragma unroll
            for (int m = 0; m < 8; m++) {
                float2 f = __half22float2(hacc[m]);
                facc[2*m] += f.x;  facc[2*m+1] += f.y;
                hacc[m] = hz;
            }
        }
    }

    // cross-warp reduce via padded smem atomics, then per-CTA partial -> g_s
#pragma unroll
    for (int d = 0; d < 16; d++) atomicAdd(&sacc[j][d], facc[d]);
    __syncthreads();
    for (int e = threadIdx.x; e < JD; e += 256) {
        int jj = e >> 4, dd = e & 15;
        atomicAdd(&g_s[b * JD + e], sacc[jj][dd]);
    }
}

// squash g_s -> (vsum | vsum+= | out), re-zero g_s. Distributed over CTAs.
template <int MODE>
__device__ __forceinline__ void squash_phase(float* __restrict__ out) {
    int bj = blockIdx.x * 256 + threadIdx.x;
    if (bj >= B * J) return;
    float4* sp = reinterpret_cast<float4*>(g_s + bj * D);
    float4 s0 = sp[0], s1 = sp[1], s2 = sp[2], s3 = sp[3];
    float n2 = 1e-7f
        + s0.x*s0.x + s0.y*s0.y + s0.z*s0.z + s0.w*s0.w
        + s1.x*s1.x + s1.y*s1.y + s1.z*s1.z + s1.w*s1.w
        + s2.x*s2.x + s2.y*s2.y + s2.z*s2.z + s2.w*s2.w
        + s3.x*s3.x + s3.y*s3.y + s3.z*s3.z + s3.w*s3.w;
    float sc = n2 / ((1.f + n2) * sqrtf(n2));

    float4 o0 = make_float4(s0.x*sc, s0.y*sc, s0.z*sc, s0.w*sc);
    float4 o1 = make_float4(s1.x*sc, s1.y*sc, s1.z*sc, s1.w*sc);
    float4 o2 = make_float4(s2.x*sc, s2.y*sc, s2.z*sc, s2.w*sc);
    float4 o3 = make_float4(s3.x*sc, s3.y*sc, s3.z*sc, s3.w*sc);

    if (MODE == 0) {
        float4* vp = reinterpret_cast<float4*>(g_vsum + bj * D);
        vp[0] = o0; vp[1] = o1; vp[2] = o2; vp[3] = o3;
    } else if (MODE == 1) {
        float4* vp = reinterpret_cast<float4*>(g_vsum + bj * D);
        float4 p0 = vp[0], p1 = vp[1], p2 = vp[2], p3 = vp[3];
        vp[0] = make_float4(p0.x+o0.x, p0.y+o0.y, p0.z+o0.z, p0.w+o0.w);
        vp[1] = make_float4(p1.x+o1.x, p1.y+o1.y, p1.z+o1.z, p1.w+o1.w);
        vp[2] = make_float4(p2.x+o2.x, p2.y+o2.y, p2.z+o2.z, p2.w+o2.w);
        vp[3] = make_float4(p3.x+o3.x, p3.y+o3.y, p3.z+o3.z, p3.w+o3.w);
    } else {
        float4* op = reinterpret_cast<float4*>(out + (size_t)bj * D);
        op[0] = o0; op[1] = o1; op[2] = o2; op[3] = o3;
    }
    float4 z = make_float4(0.f, 0.f, 0.f, 0.f);   // restore s == 0 invariant
    sp[0] = z; sp[1] = z; sp[2] = z; sp[3] = z;
}

// ---------------------------------------------------------------------------
// Persistent fused routing: all 3 phases in one launch (R13, unchanged).
// ---------------------------------------------------------------------------
__global__ __launch_bounds__(256, 4) void routing_fused(float* __restrict__ out) {
    __shared__ float sacc[J][D + 1];
    __shared__ unsigned sT0[3], sG0, sCur;

    if (threadIdx.x == 0) {
        sG0    = *(volatile unsigned*)&g_gen;
        sT0[0] = *(volatile unsigned*)&g_tick[0];
        sT0[1] = *(volatile unsigned*)&g_tick[1];
        sT0[2] = *(volatile unsigned*)&g_tick[2];
    }
    __syncthreads();
    const unsigned G0 = sG0;
    grid_bar(G0, 1);   // all CTAs snapshotted before anyone consumes

#define RUN_PHASE(MODE, IB_EXPR)                                              \
    for (;;) {                                                                \
        if (threadIdx.x == 0)                                                 \
            sCur = atomicAdd(&g_tick[MODE], 1u) - sT0[MODE];                  \
        for (int e = threadIdx.x; e < J * (D + 1); e += 256)                  \
            (&sacc[0][0])[e] = 0.f;                                           \
        __syncthreads();                                                      \
        unsigned t = sCur;                                                    \
        if (t >= (unsigned)NITEM) break;                                      \
        int b  = (int)(t & 63);                                               \
        int ti = (int)(t >> 6);                                               \
        int ib = (IB_EXPR);                                                   \
        do_item<MODE>(b, ib, sacc);                                           \
        __syncthreads();                                                      \
    }

    RUN_PHASE(0, NIB - 1 - ti)      // c = 1/32            -> s0
    grid_bar(G0, 2);
    squash_phase<0>(out);           // vsum = v0; s = 0
    grid_bar(G0, 3);
    RUN_PHASE(1, ti)                // c = softmax(u.v0)   -> s1
    grid_bar(G0, 4);
    squash_phase<1>(out);           // vsum += v1; s = 0
    grid_bar(G0, 5);
    RUN_PHASE(2, NIB - 1 - ti)      // c = softmax(u.vsum) -> s2
    grid_bar(G0, 6);
    squash_phase<2>(out);           // out = v2; s = 0
#undef RUN_PHASE
}

// ---------------------------------------------------------------------------
extern "C" void kernel_launch(void* const* d_in, const int* in_sizes, int n_in,
                              void* d_out, int out_size) {
    const float* in = (const float*)d_in[0];   // [B, I, P]
    const float* W  = (const float*)d_in[1];   // [I, J, D, P] -> [i, jd, p]
    float* out = (float*)d_out;                // [B, J, D]
    (void)in_sizes; (void)n_in; (void)out_size;

    gemm_uhat<<<I, 256>>>(in, W);
    routing_fused<<<NCTA, 256>>>(out);
}

// round 15
// speedup vs baseline: 1.1905x; 1.1905x over previous
#include <cuda_runtime.h>
#include <cuda_fp16.h>
#include <math.h>

// Problem constants (fixed by reference setup_inputs)
constexpr int B  = 64;
constexpr int I  = 2048;
constexpr int P  = 16;
constexpr int J  = 32;          // == warp size: lane j owns capsule j
constexpr int D  = 16;
constexpr int JD = J * D;       // 512

constexpr int NIB   = 32;       // i-blocks -> 2048 items per phase
constexpr int IPB   = I / NIB;  // 64 i's per item
constexpr int NITEM = NIB * B;  // 2048
constexpr int NCTA  = 592;      // 148 SMs x 4 CTAs (co-resident on 148/152-SM parts)

// Scratch (device globals; zero-initialized at load; invariants restored per run)
__device__ __half g_uhat[(size_t)B * I * JD];  // 128 MB fp16  [b,i,j,d]
__device__ float  g_s[B * J * D];              // 128 KB  s accumulator (starts 0)
__device__ float  g_vsum[B * J * D];           // 128 KB  running v0(+v1)
__device__ unsigned g_tick[3];                 // monotonic ticket counters
__device__ unsigned g_arrive;                  // barrier arrive (self-resetting)
__device__ unsigned g_gen;                     // barrier generation (monotonic)

// ---- packed f32x2 helpers (gemm) -------------------------------------------
#define FMA_X2(a, x, c) asm("fma.rn.f32x2 %0, %1, %2, %0;" : "+l"(a) : "l"(x), "l"(c))

// ---------------------------------------------------------------------------
// Kernel 1: u_hat[b,i,jd] = sum_p inputs[b,i,p] * W[i,jd,p], stored fp16.
// One CTA per i (R13 body, proven fastest shape). Thread t owns jd pair
// (2t, 2t+1); batches in pairs -> each fma.rn.f32x2 does 2 MACs.
// R15: x batch-pair loaded DIRECTLY as a 64-bit smem word (no pack movs;
// row stride 264 B keeps 8-byte alignment), and __launch_bounds__(256,3)
// lifts occupancy 2 -> 3 CTAs/SM (fits the ~82-reg natural footprint).
// ---------------------------------------------------------------------------
__global__ __launch_bounds__(256, 3) void gemm_uhat(const float* __restrict__ in,
                                                    const float* __restrict__ W) {
    const int i = blockIdx.x;
    const int t = threadIdx.x;

    __shared__ __align__(16) float Ws[JD * 17];    // padded rows: bank-safe
    __shared__ __align__(16) float insT[P][B + 2]; // p-major, stride 66: 8B-aligned pairs

    // stage W[i] (32 KB, streaming hint: keep u_hat resident in L2 instead)
    const float4* Wg = reinterpret_cast<const float4*>(W + (size_t)i * JD * P);
#pragma unroll
    for (int k = 0; k < 8; k++) {
        int e = t + k * 256;             // float4 index 0..2047
        float4 v = __ldcs(&Wg[e]);
        float* dst = &Ws[(e >> 2) * 17 + (e & 3) * 4];
        dst[0] = v.x; dst[1] = v.y; dst[2] = v.z; dst[3] = v.w;
    }
    // stage inputs[:, i, :] transposed -> insT[p][b]
#pragma unroll
    for (int k = 0; k < 4; k++) {
        int e = t + k * 256;             // 0..1023
        int b = e >> 4, p = e & 15;
        insT[p][b] = in[((size_t)b * I + i) * P + p];
    }
    __syncthreads();

    // splat W rows for jd0=2t, jd1=2t+1 into f32x2 registers (once)
    const int jd0 = 2 * t;
    unsigned long long w0[16], w1[16];
#pragma unroll
    for (int p = 0; p < 16; p++) {
        float a = Ws[jd0 * 17 + p];
        float b = Ws[(jd0 + 1) * 17 + p];
        asm("mov.b64 %0,{%1,%1};" : "=l"(w0[p]) : "f"(a));
        asm("mov.b64 %0,{%1,%1};" : "=l"(w1[p]) : "f"(b));
    }

    __half* ubase = g_uhat + (size_t)i * JD + jd0;
#pragma unroll 2
    for (int q = 0; q < 32; q++) {       // batch pair (2q, 2q+1)
        unsigned long long a0 = 0ull, a1 = 0ull;  // (0.f,0.f) packed
#pragma unroll
        for (int p = 0; p < 16; p++) {
            // (x_{b0,p}, x_{b1,p}) straight from one LDS.64 -- no pack mov
            unsigned long long x =
                *reinterpret_cast<const unsigned long long*>(&insT[p][2 * q]);
            FMA_X2(a0, x, w0[p]);
            FMA_X2(a1, x, w1[p]);
        }
        float a0lo, a0hi, a1lo, a1hi;
        asm("mov.b64 {%0,%1}, %2;" : "=f"(a0lo), "=f"(a0hi) : "l"(a0));
        asm("mov.b64 {%0,%1}, %2;" : "=f"(a1lo), "=f"(a1hi) : "l"(a1));
        __half2 hb0 = __floats2half2_rn(a0lo, a1lo);   // b0: (jd0, jd1)
        __half2 hb1 = __floats2half2_rn(a0hi, a1hi);   // b1: (jd0, jd1)
        *reinterpret_cast<__half2*>(ubase + (size_t)(2 * q) * I * JD)     = hb0;
        *reinterpret_cast<__half2*>(ubase + (size_t)(2 * q + 1) * I * JD) = hb1;
    }
}

// ---------------------------------------------------------------------------
// Grid barrier: arrive counter (self-resetting) + monotonic generation.
// base = generation snapshot at kernel entry; target = base + k. Wrap-safe,
// replay-safe (no resets). All NCTA CTAs are co-resident by construction.
// ---------------------------------------------------------------------------
__device__ __forceinline__ void grid_bar(unsigned base, unsigned k) {
    __syncthreads();
    if (threadIdx.x == 0) {
        __threadfence();
        if (atomicAdd(&g_arrive, 1u) == NCTA - 1) {
            g_arrive = 0;
            __threadfence();
            atomicExch(&g_gen, base + k);
        } else {
            while ((unsigned)(*(volatile unsigned*)&g_gen - base) < k)
                __nanosleep(64);
        }
        __threadfence();
    }
    __syncthreads();
}

// ---------------------------------------------------------------------------
// One routing item (b, ib): R11/R13 compute body (IPB=64).
//   MODE 0: c = 1/32.   MODE 1/2: c = softmax_j(u . vsum), ILP-2 butterflies.
// fp16 HFMA2 dot + fp16 accumulate flushed to fp32 every 4 i's.
// ---------------------------------------------------------------------------
template <int MODE>
__device__ __forceinline__ void do_item(int b, int ib, float (*sacc)[D + 1]) {
    const int w = threadIdx.x >> 5;
    const int j = threadIdx.x & 31;

    __half2 hv[8];
    if (MODE > 0) {
        const float4* vp = reinterpret_cast<const float4*>(g_vsum + (b * J + j) * D);
#pragma unroll
        for (int k = 0; k < 4; k++) {
            float4 q = vp[k];
            hv[2*k]   = __floats2half2_rn(q.x, q.y);
            hv[2*k+1] = __floats2half2_rn(q.z, q.w);
        }
    }

    float  facc[16];
    __half2 hacc[8];
    const __half2 hz = __floats2half2_rn(0.f, 0.f);
#pragma unroll
    for (int d = 0; d < 16; d++) facc[d] = 0.f;
#pragma unroll
    for (int m = 0; m < 8; m++) hacc[m] = hz;

    const size_t row = (size_t)b * I + (size_t)ib * IPB;

    if (MODE == 0) {
#pragma unroll
        for (int ii = 0; ii < IPB; ii += 32) {
#pragma unroll
            for (int k = 0; k < 4; k++) {
                const __half* up = g_uhat + (row + w + ii + 8 * k) * JD + j * D;
                uint4 q0 = *reinterpret_cast<const uint4*>(up);
                uint4 q1 = *reinterpret_cast<const uint4*>(up + 8);
                const __half2* h0 = reinterpret_cast<const __half2*>(&q0);
                const __half2* h1 = reinterpret_cast<const __half2*>(&q1);
#pragma unroll
                for (int m = 0; m < 4; m++) {
                    hacc[m]   = __hadd2(hacc[m],   h0[m]);
                    hacc[4+m] = __hadd2(hacc[4+m], h1[m]);
                }
            }
#pragma unroll
            for (int m = 0; m < 8; m++) {
                float2 f = __half22float2(hacc[m]);
                facc[2*m] += f.x;  facc[2*m+1] += f.y;
                hacc[m] = hz;
            }
        }
#pragma unroll
        for (int d = 0; d < 16; d++) facc[d] *= (1.f / 32.f);
    } else {
#pragma unroll
        for (int gg = 0; gg < IPB / 32; gg++) {
#pragma unroll
            for (int h = 0; h < 2; h++) {
                const int g = 2 * gg + h;
                const __half* upA = g_uhat + (row + w + 16 * g) * JD + j * D;
                const __half* upB = upA + 8 * JD;
                uint4 qa0 = *reinterpret_cast<const uint4*>(upA);
                uint4 qa1 = *reinterpret_cast<const uint4*>(upA + 8);
                uint4 qb0 = *reinterpret_cast<const uint4*>(upB);
                uint4 qb1 = *reinterpret_cast<const uint4*>(upB + 8);
                const __half2* ha0 = reinterpret_cast<const __half2*>(&qa0);
                const __half2* ha1 = reinterpret_cast<const __half2*>(&qa1);
                const __half2* hb0 = reinterpret_cast<const __half2*>(&qb0);
                const __half2* hb1 = reinterpret_cast<const __half2*>(&qb1);

                __half2 dA = __hmul2(ha0[0], hv[0]);
                __half2 dB = __hmul2(hb0[0], hv[0]);
#pragma unroll
                for (int m = 1; m < 4; m++) {
                    dA = __hfma2(ha0[m], hv[m], dA);
                    dB = __hfma2(hb0[m], hv[m], dB);
                }
#pragma unroll
                for (int m = 0; m < 4; m++) {
                    dA = __hfma2(ha1[m], hv[4+m], dA);
                    dB = __hfma2(hb1[m], hv[4+m], dB);
                }
                float2 fA = __half22float2(dA);
                float2 fB = __half22float2(dB);
                float tA = fA.x + fA.y;
                float tB = fB.x + fB.y;

                float eA = __expf(tA);
                float eB = __expf(tB);
                float sA = eA, sB = eB;
#pragma unroll
                for (int off = 16; off; off >>= 1) {
                    sA += __shfl_xor_sync(0xffffffffu, sA, off);
                    sB += __shfl_xor_sync(0xffffffffu, sB, off);
                }
                __half2 cA2 = __float2half2_rn(__fdividef(eA, sA));
                __half2 cB2 = __float2half2_rn(__fdividef(eB, sB));

#pragma unroll
                for (int m = 0; m < 4; m++) {
                    hacc[m]   = __hfma2(ha0[m], cA2, hacc[m]);
                    hacc[4+m] = __hfma2(ha1[m], cA2, hacc[4+m]);
                    hacc[m]   = __hfma2(hb0[m], cB2, hacc[m]);
                    hacc[4+m] = __hfma2(hb1[m], cB2, hacc[4+m]);
                }
            }
#pragma unroll
            for (int m = 0; m < 8; m++) {
                float2 f = __half22float2(hacc[m]);
                facc[2*m] += f.x;  facc[2*m+1] += f.y;
                hacc[m] = hz;
            }
        }
    }

    // cross-warp reduce via padded smem atomics, then per-CTA partial -> g_s
#pragma unroll
    for (int d = 0; d < 16; d++) atomicAdd(&sacc[j][d], facc[d]);
    __syncthreads();
    for (int e = threadIdx.x; e < JD; e += 256) {
        int jj = e >> 4, dd = e & 15;
        atomicAdd(&g_s[b * JD + e], sacc[jj][dd]);
    }
}

// squash g_s -> (vsum | vsum+= | out), re-zero g_s. Distributed over CTAs.
template <int MODE>
__device__ __forceinline__ void squash_phase(float* __restrict__ out) {
    int bj = blockIdx.x * 256 + threadIdx.x;
    if (bj >= B * J) return;
    float4* sp = reinterpret_cast<float4*>(g_s + bj * D);
    float4 s0 = sp[0], s1 = sp[1], s2 = sp[2], s3 = sp[3];
    float n2 = 1e-7f
        + s0.x*s0.x + s0.y*s0.y + s0.z*s0.z + s0.w*s0.w
        + s1.x*s1.x + s1.y*s1.y + s1.z*s1.z + s1.w*s1.w
        + s2.x*s2.x + s2.y*s2.y + s2.z*s2.z + s2.w*s2.w
        + s3.x*s3.x + s3.y*s3.y + s3.z*s3.z + s3.w*s3.w;
    float sc = n2 / ((1.f + n2) * sqrtf(n2));

    float4 o0 = make_float4(s0.x*sc, s0.y*sc, s0.z*sc, s0.w*sc);
    float4 o1 = make_float4(s1.x*sc, s1.y*sc, s1.z*sc, s1.w*sc);
    float4 o2 = make_float4(s2.x*sc, s2.y*sc, s2.z*sc, s2.w*sc);
    float4 o3 = make_float4(s3.x*sc, s3.y*sc, s3.z*sc, s3.w*sc);

    if (MODE == 0) {
        float4* vp = reinterpret_cast<float4*>(g_vsum + bj * D);
        vp[0] = o0; vp[1] = o1; vp[2] = o2; vp[3] = o3;
    } else if (MODE == 1) {
        float4* vp = reinterpret_cast<float4*>(g_vsum + bj * D);
        float4 p0 = vp[0], p1 = vp[1], p2 = vp[2], p3 = vp[3];
        vp[0] = make_float4(p0.x+o0.x, p0.y+o0.y, p0.z+o0.z, p0.w+o0.w);
        vp[1] = make_float4(p1.x+o1.x, p1.y+o1.y, p1.z+o1.z, p1.w+o1.w);
        vp[2] = make_float4(p2.x+o2.x, p2.y+o2.y, p2.z+o2.z, p2.w+o2.w);
        vp[3] = make_float4(p3.x+o3.x, p3.y+o3.y, p3.z+o3.z, p3.w+o3.w);
    } else {
        float4* op = reinterpret_cast<float4*>(out + (size_t)bj * D);
        op[0] = o0; op[1] = o1; op[2] = o2; op[3] = o3;
    }
    float4 z = make_float4(0.f, 0.f, 0.f, 0.f);   // restore s == 0 invariant
    sp[0] = z; sp[1] = z; sp[2] = z; sp[3] = z;
}

// ---------------------------------------------------------------------------
// Persistent fused routing: all 3 phases in one launch (R13, unchanged).
// ---------------------------------------------------------------------------
__global__ __launch_bounds__(256, 4) void routing_fused(float* __restrict__ out) {
    __shared__ float sacc[J][D + 1];
    __shared__ unsigned sT0[3], sG0, sCur;

    if (threadIdx.x == 0) {
        sG0    = *(volatile unsigned*)&g_gen;
        sT0[0] = *(volatile unsigned*)&g_tick[0];
        sT0[1] = *(volatile unsigned*)&g_tick[1];
        sT0[2] = *(volatile unsigned*)&g_tick[2];
    }
    __syncthreads();
    const unsigned G0 = sG0;
    grid_bar(G0, 1);   // all CTAs snapshotted before anyone consumes

#define RUN_PHASE(MODE, IB_EXPR)                                              \
    for (;;) {                                                                \
        if (threadIdx.x == 0)                                                 \
            sCur = atomicAdd(&g_tick[MODE], 1u) - sT0[MODE];                  \
        for (int e = threadIdx.x; e < J * (D + 1); e += 256)                  \
            (&sacc[0][0])[e] = 0.f;                                           \
        __syncthreads();                                                      \
        unsigned t = sCur;                                                    \
        if (t >= (unsigned)NITEM) break;                                      \
        int b  = (int)(t & 63);                                               \
        int ti = (int)(t >> 6);                                               \
        int ib = (IB_EXPR);                                                   \
        do_item<MODE>(b, ib, sacc);                                           \
        __syncthreads();                                                      \
    }

    RUN_PHASE(0, NIB - 1 - ti)      // c = 1/32            -> s0
    grid_bar(G0, 2);
    squash_phase<0>(out);           // vsum = v0; s = 0
    grid_bar(G0, 3);
    RUN_PHASE(1, ti)                // c = softmax(u.v0)   -> s1
    grid_bar(G0, 4);
    squash_phase<1>(out);           // vsum += v1; s = 0
    grid_bar(G0, 5);
    RUN_PHASE(2, NIB - 1 - ti)      // c = softmax(u.vsum) -> s2
    grid_bar(G0, 6);
    squash_phase<2>(out);           // out = v2; s = 0
#undef RUN_PHASE
}

// ---------------------------------------------------------------------------
extern "C" void kernel_launch(void* const* d_in, const int* in_sizes, int n_in,
                              void* d_out, int out_size) {
    const float* in = (const float*)d_in[0];   // [B, I, P]
    const float* W  = (const float*)d_in[1];   // [I, J, D, P] -> [i, jd, p]
    float* out = (float*)d_out;                // [B, J, D]
    (void)in_sizes; (void)n_in; (void)out_size;

    gemm_uhat<<<I, 256>>>(in, W);
    routing_fused<<<NCTA, 256>>>(out);
}